// round 12
// baseline (speedup 1.0000x reference)
#include <cuda_runtime.h>
#include <math.h>

#define N_NODES 100000
#define N_EDGES 3200000
#define IN_DIM 256
#define EMB_DIM 64
#define BATCH 4096
#define CAP 96                                       // bucket capacity per row

#define TILE_M 64
#define NGEMM ((N_NODES + TILE_M - 1) / TILE_M)     // 1563 gemm tiles
#define NFUSED (NGEMM * 2)                          // interleaved gemm/scatter blocks

// ---------------- device scratch (no allocation allowed) ----------------
__device__ unsigned  g_xw[(size_t)N_NODES * 32];    // bf16x2 packed, 2 dims/word
__device__ unsigned  g_wb[EMB_DIM * 128];           // W bf16x2, [n][kword], 32KB
__device__ float     g_h[(size_t)N_NODES * EMB_DIM];
__device__ int       g_cnt[N_NODES];                // bucket cursor == row degree
__device__ int2      g_csr[(size_t)N_NODES * CAP];  // {col, float_bits(val)} buckets
__device__ int       g_done;
__device__ float     g_acc[2];                      // [0]=sum(emb^2), [1]=bpr

static __device__ __forceinline__ unsigned bf16x2_of(float hi, float lo) {
    unsigned r;
    asm("cvt.rn.bf16x2.f32 %0, %1, %2;" : "=r"(r) : "f"(hi), "f"(lo));
    return r;
}

// ---------------------------------------------------------------------------
// Launch 0 (tiny, 32 blocks): convert W (256x64 fp32) -> g_wb[n][kword]
// bf16x2 frag layout; block 0 zeroes scalar state.
// ---------------------------------------------------------------------------
__global__ void prep_kernel(const float* __restrict__ W) {
    if (blockIdx.x == 0 && threadIdx.x == 0) {
        g_acc[0] = 0.f; g_acc[1] = 0.f; g_done = 0;
    }
    int idx = blockIdx.x * 256 + threadIdx.x;        // 8192 total
    if (idx < EMB_DIM * 128) {
        int n  = idx >> 7;          // 0..63
        int kw = idx & 127;         // k-pair 0..127
        float lo = W[(size_t)(2 * kw)     * EMB_DIM + n];
        float hi = W[(size_t)(2 * kw + 1) * EMB_DIM + n];
        g_wb[n * 128 + kw] = bf16x2_of(hi, lo);
    }
}

// ---------------------------------------------------------------------------
// Launch 1 (FUSED): even blocks = 64x64 HMMA GEMM tile (B frags from
// L1-resident g_wb), odd blocks = bucket scatter (4 edges/thread).
// launch_bounds(256,5): 51-reg cap — known to fit (R9: 48 regs). (256,6)
// capped at 40 regs and spilled the MMA accumulators — 90us regression.
// ---------------------------------------------------------------------------
__global__ __launch_bounds__(256, 5) void gemm_scatter_kernel(
        const float* __restrict__ feats,
        const int* __restrict__ erow, const int* __restrict__ ecol,
        const float* __restrict__ evalv) {
    if (blockIdx.x & 1) {
        // ---- scatter role: 4 consecutive edges per thread via 128b loads ----
        const int nquads  = N_EDGES / 4;              // 800000
        const int qstride = NGEMM * 256;              // total scatter threads
        for (int q = (blockIdx.x >> 1) * 256 + threadIdx.x; q < nquads; q += qstride) {
            int4   r4 = ((const int4*)erow)[q];
            int4   c4 = ((const int4*)ecol)[q];
            float4 v4 = ((const float4*)evalv)[q];
            int p0 = atomicAdd(&g_cnt[r4.x], 1);
            int p1 = atomicAdd(&g_cnt[r4.y], 1);
            int p2 = atomicAdd(&g_cnt[r4.z], 1);
            int p3 = atomicAdd(&g_cnt[r4.w], 1);
            if (p0 < CAP) g_csr[(size_t)r4.x * CAP + p0] = make_int2(c4.x, __float_as_int(v4.x));
            if (p1 < CAP) g_csr[(size_t)r4.y * CAP + p1] = make_int2(c4.y, __float_as_int(v4.y));
            if (p2 < CAP) g_csr[(size_t)r4.z * CAP + p2] = make_int2(c4.z, __float_as_int(v4.z));
            if (p3 < CAP) g_csr[(size_t)r4.w * CAP + p3] = make_int2(c4.w, __float_as_int(v4.w));
        }
        return;
    }

    // ---- GEMM role: xw[row0..row0+63][0..63] via mma.m16n8k16 bf16 ----
    __shared__ __align__(16) unsigned As[TILE_M * 36];   // A: [row][kword]

    const int row0 = (blockIdx.x >> 1) * TILE_M;
    const int tid  = threadIdx.x;
    const int wp   = tid >> 5;          // 0..7
    const int l    = tid & 31;
    const int lq   = l >> 2;            // 0..7
    const int lr4  = l & 3;             // 0..3
    const int wrow0 = (wp & 3) * 16;
    const int ncol0 = (wp >> 2) * 32;   // 0 or 32

    float c[4][4];
#pragma unroll
    for (int j = 0; j < 4; j++)
#pragma unroll
        for (int q = 0; q < 4; q++) c[j][q] = 0.f;

    for (int kb = 0; kb < IN_DIM; kb += 64) {
        // --- fill A: 64 rows x 64 k, fully coalesced (16 lanes = 256B/row) ---
#pragma unroll
        for (int i = 0; i < 4; i++) {
            int idx = tid + 256 * i;               // 0..1023
            int r   = idx >> 4;                    // row 0..63
            int j4  = idx & 15;                    // float4 index
            int grow = row0 + r;
            float4 f = make_float4(0.f, 0.f, 0.f, 0.f);
            if (grow < N_NODES)
                f = *(const float4*)&feats[(size_t)grow * IN_DIM + kb + 4 * j4];
            uint2 w2 = make_uint2(bf16x2_of(f.y, f.x), bf16x2_of(f.w, f.z));
            *(uint2*)&As[r * 36 + 2 * j4] = w2;
        }
        __syncthreads();

        // --- 4 k-steps of 16; B frags from L1-resident g_wb ---
#pragma unroll
        for (int ks = 0; ks < 4; ks++) {
            const int kw  = ks * 8 + lr4;              // smem kword
            const int kwg = (kb >> 1) + kw;            // global kword
            unsigned a0 = As[(wrow0 + lq) * 36 + kw];
            unsigned a1 = As[(wrow0 + lq + 8) * 36 + kw];
            unsigned a2 = As[(wrow0 + lq) * 36 + kw + 4];
            unsigned a3 = As[(wrow0 + lq + 8) * 36 + kw + 4];
#pragma unroll
            for (int j = 0; j < 4; j++) {
                unsigned b0 = g_wb[(ncol0 + 8 * j + lq) * 128 + kwg];
                unsigned b1 = g_wb[(ncol0 + 8 * j + lq) * 128 + kwg + 4];
                asm volatile(
                    "mma.sync.aligned.m16n8k16.row.col.f32.bf16.bf16.f32 "
                    "{%0,%1,%2,%3}, {%4,%5,%6,%7}, {%8,%9}, {%0,%1,%2,%3};"
                    : "+f"(c[j][0]), "+f"(c[j][1]), "+f"(c[j][2]), "+f"(c[j][3])
                    : "r"(a0), "r"(a1), "r"(a2), "r"(a3), "r"(b0), "r"(b1));
            }
        }
        __syncthreads();
    }

    // --- write bf16x2 output ---
    {
        const int r0 = row0 + wrow0 + lq;
        const int r1 = r0 + 8;
#pragma unroll
        for (int j = 0; j < 4; j++) {
            unsigned wlo = bf16x2_of(c[j][1], c[j][0]);
            unsigned whi = bf16x2_of(c[j][3], c[j][2]);
            int wcol = (ncol0 >> 1) + 4 * j + lr4;
            if (r0 < N_NODES) g_xw[(size_t)r0 * 32 + wcol] = wlo;
            if (r1 < N_NODES) g_xw[(size_t)r1 * 32 + wcol] = whi;
        }
    }
}

// ---------------------------------------------------------------------------
// Launch 2: fused bucket gather + tanh + l2-normalize + sum(emb^2).
// One warp per row. Also RESETS g_cnt[row]=0 so no memset is needed.
// ---------------------------------------------------------------------------
__global__ __launch_bounds__(256) void row_kernel() {
    __shared__ int2  stage[8][32];
    __shared__ float ssum;
    const int wib  = threadIdx.x >> 5;
    const int row  = (blockIdx.x * 256 + threadIdx.x) >> 5;
    const int lane = threadIdx.x & 31;
    const int grp  = lane >> 3;
    const int subw = (lane & 7) << 2;       // word offset of this lane's 4 words
    if (threadIdx.x == 0) ssum = 0.f;
    __syncthreads();

    if (row < N_NODES) {
        const int len = min(g_cnt[row], CAP);
        if (lane == 0) g_cnt[row] = 0;       // self-clean for next graph replay
        const int2* __restrict__ bucket = &g_csr[(size_t)row * CAP];
        float acc[8];
#pragma unroll
        for (int k = 0; k < 8; k++) acc[k] = 0.f;

        for (int base = 0; base < len; base += 32) {
            int j = base + lane;
            stage[wib][lane] = (j < len) ? bucket[j] : make_int2(0, 0);
            __syncwarp();
            int m4 = (min(32, len - base) + 3) & ~3;    // val=0 pads are no-ops
            for (int t = 0; t < m4; t += 4) {
                int2 cv = stage[wib][t + grp];
                const uint4 u = *(const uint4*)(g_xw + (unsigned)(cv.x * 32) + subw);
                float v = __int_as_float(cv.y);
                acc[0] = fmaf(v, __uint_as_float(u.x << 16),          acc[0]);
                acc[1] = fmaf(v, __uint_as_float(u.x & 0xffff0000u),  acc[1]);
                acc[2] = fmaf(v, __uint_as_float(u.y << 16),          acc[2]);
                acc[3] = fmaf(v, __uint_as_float(u.y & 0xffff0000u),  acc[3]);
                acc[4] = fmaf(v, __uint_as_float(u.z << 16),          acc[4]);
                acc[5] = fmaf(v, __uint_as_float(u.z & 0xffff0000u),  acc[5]);
                acc[6] = fmaf(v, __uint_as_float(u.w << 16),          acc[6]);
                acc[7] = fmaf(v, __uint_as_float(u.w & 0xffff0000u),  acc[7]);
            }
            __syncwarp();
        }

        // combine the 4 edge groups (lane bits 3,4)
#pragma unroll
        for (int k = 0; k < 8; k++) {
            acc[k] += __shfl_xor_sync(0xffffffffu, acc[k], 8);
            acc[k] += __shfl_xor_sync(0xffffffffu, acc[k], 16);
        }
        float h[8];
        float sq = 0.f;
#pragma unroll
        for (int k = 0; k < 8; k++) { h[k] = tanhf(acc[k]); sq = fmaf(h[k], h[k], sq); }
#pragma unroll
        for (int o = 1; o < 8; o <<= 1) sq += __shfl_xor_sync(0xffffffffu, sq, o);
        float rs = rsqrtf(fmaxf(sq, 1e-12f));
        if (grp == 0) {   // lanes 0..7 write the full 64-dim row
            *(float4*)&g_h[(size_t)row * EMB_DIM + subw * 2] =
                make_float4(h[0] * rs, h[1] * rs, h[2] * rs, h[3] * rs);
            *(float4*)&g_h[(size_t)row * EMB_DIM + subw * 2 + 4] =
                make_float4(h[4] * rs, h[5] * rs, h[6] * rs, h[7] * rs);
        }
        // weight decay needs sum over NORMALIZED emb: sq * rs^2
        if (lane == 0) atomicAdd(&ssum, sq * rs * rs);
    }
    __syncthreads();
    if (threadIdx.x == 0) atomicAdd(&g_acc[0], ssum);
}

// ---------------------------------------------------------------------------
// Launch 3: BPR loss + fused finalize (last block writes the scalar out).
// ---------------------------------------------------------------------------
__global__ __launch_bounds__(256) void loss_kernel(const int* __restrict__ idx1,
                                                   const int* __restrict__ idx2,
                                                   const int* __restrict__ negi,
                                                   float* __restrict__ out) {
    int b    = (blockIdx.x * blockDim.x + threadIdx.x) >> 5;
    int lane = threadIdx.x & 31;
    __shared__ float ssum;
    if (threadIdx.x == 0) ssum = 0.f;
    __syncthreads();

    if (b < BATCH) {
        int i1 = idx1[b], i2 = idx2[b], in_ = negi[b];
        float2 e1 = *(float2*)&g_h[(size_t)i1 * EMB_DIM + lane * 2];
        float2 e2 = *(float2*)&g_h[(size_t)i2 * EMB_DIM + lane * 2];
        float2 en = *(float2*)&g_h[(size_t)in_ * EMB_DIM + lane * 2];
        float dui = e1.x * e2.x + e1.y * e2.y;
        float duj = e1.x * en.x + e1.y * en.y;
#pragma unroll
        for (int o = 16; o > 0; o >>= 1) {
            dui += __shfl_xor_sync(0xffffffffu, dui, o);
            duj += __shfl_xor_sync(0xffffffffu, duj, o);
        }
        if (lane == 0) {
            float z = duj - dui;  // -log_sigmoid(dui-duj) = softplus(duj-dui)
            float term = fmaxf(z, 0.f) + log1pf(expf(-fabsf(z)));
            atomicAdd(&ssum, term);
        }
    }
    __syncthreads();
    if (threadIdx.x == 0) {
        atomicAdd(&g_acc[1], ssum);
        __threadfence();
        int d = atomicAdd(&g_done, 1);
        if (d == (int)gridDim.x - 1) {
            float bpr = atomicAdd(&g_acc[1], 0.f);   // L2-coherent reads
            float ss  = atomicAdd(&g_acc[0], 0.f);
            out[0] = (bpr + 1e-4f * 0.5f * ss) / (float)BATCH;
        }
    }
}

// ---------------------------------------------------------------------------
extern "C" void kernel_launch(void* const* d_in, const int* in_sizes, int n_in,
                              void* d_out, int out_size) {
    const float* feats = (const float*)d_in[0];
    const float* W     = (const float*)d_in[1];
    const int*   erow  = (const int*)d_in[2];
    const int*   ecol  = (const int*)d_in[3];
    const float* evalv = (const float*)d_in[4];
    const int*   idx1  = (const int*)d_in[5];
    const int*   idx2  = (const int*)d_in[6];
    const int*   negi  = (const int*)d_in[7];

    prep_kernel<<<32, 256>>>(W);
    gemm_scatter_kernel<<<NFUSED, 256>>>(feats, erow, ecol, evalv);
    row_kernel<<<(N_NODES * 32 + 255) / 256, 256>>>();
    loss_kernel<<<(BATCH * 32) / 256, 256>>>(idx1, idx2, negi, (float*)d_out);
}

// round 13
// speedup vs baseline: 1.2075x; 1.2075x over previous
#include <cuda_runtime.h>
#include <math.h>

#define N_NODES 100000
#define N_EDGES 3200000
#define IN_DIM 256
#define EMB_DIM 64
#define BATCH 4096
#define CAP 96                                       // bucket capacity per row

#define TILE_M 64
#define NGEMM ((N_NODES + TILE_M - 1) / TILE_M)     // 1563 gemm tiles
#define NFUSED (NGEMM * 2)                          // interleaved gemm/scatter blocks

// ---------------- device scratch (no allocation allowed) ----------------
__device__ unsigned  g_xw[(size_t)N_NODES * 32];    // bf16x2 packed, 2 dims/word
__device__ unsigned  g_wb[EMB_DIM * 128];           // W bf16x2, [n][kword], 32KB
__device__ float     g_h[(size_t)N_NODES * EMB_DIM];
__device__ int       g_cnt[N_NODES];                // bucket cursor == row degree
__device__ int2      g_csr[(size_t)N_NODES * CAP];  // {col, float_bits(val)} buckets
__device__ int       g_done;
__device__ float     g_acc[2];                      // [0]=sum(emb^2), [1]=bpr

static __device__ __forceinline__ unsigned bf16x2_of(float hi, float lo) {
    unsigned r;
    asm("cvt.rn.bf16x2.f32 %0, %1, %2;" : "=r"(r) : "f"(hi), "f"(lo));
    return r;
}

// ---------------------------------------------------------------------------
// Launch 0 (tiny, 32 blocks): convert W (256x64 fp32) -> g_wb[n][kword]
// bf16x2 frag layout; block 0 zeroes scalar state.
// ---------------------------------------------------------------------------
__global__ void prep_kernel(const float* __restrict__ W) {
    if (blockIdx.x == 0 && threadIdx.x == 0) {
        g_acc[0] = 0.f; g_acc[1] = 0.f; g_done = 0;
    }
    int idx = blockIdx.x * 256 + threadIdx.x;        // 8192 total
    if (idx < EMB_DIM * 128) {
        int n  = idx >> 7;          // 0..63
        int kw = idx & 127;         // k-pair 0..127
        float lo = W[(size_t)(2 * kw)     * EMB_DIM + n];
        float hi = W[(size_t)(2 * kw + 1) * EMB_DIM + n];
        g_wb[n * 128 + kw] = bf16x2_of(hi, lo);
    }
}

// ---------------------------------------------------------------------------
// Launch 1 (FUSED): even blocks = 64x64 HMMA GEMM tile (A and B both staged
// in smem; B copied from pre-converted g_wb with plain uint4 moves — no cvt,
// no transpose), odd blocks = bucket scatter (4 edges/thread).
// NOTE: B frags read directly from global (R10/R12) cost +80us — the LDG.32s
// (512B stride, 8 lines/warp) sit in the HMMA dependency chain. Keep B in smem.
// ---------------------------------------------------------------------------
__global__ __launch_bounds__(256, 5) void gemm_scatter_kernel(
        const float* __restrict__ feats,
        const int* __restrict__ erow, const int* __restrict__ ecol,
        const float* __restrict__ evalv) {
    if (blockIdx.x & 1) {
        // ---- scatter role: 4 consecutive edges per thread via 128b loads ----
        const int nquads  = N_EDGES / 4;              // 800000
        const int qstride = NGEMM * 256;              // total scatter threads
        for (int q = (blockIdx.x >> 1) * 256 + threadIdx.x; q < nquads; q += qstride) {
            int4   r4 = ((const int4*)erow)[q];
            int4   c4 = ((const int4*)ecol)[q];
            float4 v4 = ((const float4*)evalv)[q];
            int p0 = atomicAdd(&g_cnt[r4.x], 1);
            int p1 = atomicAdd(&g_cnt[r4.y], 1);
            int p2 = atomicAdd(&g_cnt[r4.z], 1);
            int p3 = atomicAdd(&g_cnt[r4.w], 1);
            if (p0 < CAP) g_csr[(size_t)r4.x * CAP + p0] = make_int2(c4.x, __float_as_int(v4.x));
            if (p1 < CAP) g_csr[(size_t)r4.y * CAP + p1] = make_int2(c4.y, __float_as_int(v4.y));
            if (p2 < CAP) g_csr[(size_t)r4.z * CAP + p2] = make_int2(c4.z, __float_as_int(v4.z));
            if (p3 < CAP) g_csr[(size_t)r4.w * CAP + p3] = make_int2(c4.w, __float_as_int(v4.w));
        }
        return;
    }

    // ---- GEMM role: xw[row0..row0+63][0..63] via mma.m16n8k16 bf16 ----
    __shared__ __align__(16) unsigned As[TILE_M * 36];   // A: [row][kword]
    __shared__ __align__(16) unsigned Bs[EMB_DIM * 36];  // B: [n][kword]

    const int row0 = (blockIdx.x >> 1) * TILE_M;
    const int tid  = threadIdx.x;
    const int wp   = tid >> 5;          // 0..7
    const int l    = tid & 31;
    const int lq   = l >> 2;            // 0..7
    const int lr4  = l & 3;             // 0..3
    const int wrow0 = (wp & 3) * 16;
    const int ncol0 = (wp >> 2) * 32;   // 0 or 32

    float c[4][4];
#pragma unroll
    for (int j = 0; j < 4; j++)
#pragma unroll
        for (int q = 0; q < 4; q++) c[j][q] = 0.f;

    for (int kb = 0; kb < IN_DIM; kb += 64) {
        // --- fill A: 64 rows x 64 k, fully coalesced (16 lanes = 256B/row) ---
#pragma unroll
        for (int i = 0; i < 4; i++) {
            int idx = tid + 256 * i;               // 0..1023
            int r   = idx >> 4;                    // row 0..63
            int j4  = idx & 15;                    // float4 index
            int grow = row0 + r;
            float4 f = make_float4(0.f, 0.f, 0.f, 0.f);
            if (grow < N_NODES)
                f = *(const float4*)&feats[(size_t)grow * IN_DIM + kb + 4 * j4];
            uint2 w2 = make_uint2(bf16x2_of(f.y, f.x), bf16x2_of(f.w, f.z));
            *(uint2*)&As[r * 36 + 2 * j4] = w2;
        }
        // --- fill B: straight uint4 copy from pre-converted g_wb ---
        // per kb: 64 n-rows x 32 kwords = 512 uint4; 2 per thread.
        {
            const int kwg0 = kb >> 1;              // first global kword this kb
#pragma unroll
            for (int s = tid; s < 512; s += 256) {
                int n  = s >> 3;                   // 0..63
                int wq = s & 7;                    // uint4 index (4 kwords)
                uint4 v = *(const uint4*)&g_wb[n * 128 + kwg0 + 4 * wq];
                *(uint4*)&Bs[n * 36 + 4 * wq] = v;
            }
        }
        __syncthreads();

        // --- 4 k-steps of 16; A and B frags from smem ---
#pragma unroll
        for (int ks = 0; ks < 4; ks++) {
            const int kw = ks * 8 + lr4;
            unsigned a0 = As[(wrow0 + lq) * 36 + kw];
            unsigned a1 = As[(wrow0 + lq + 8) * 36 + kw];
            unsigned a2 = As[(wrow0 + lq) * 36 + kw + 4];
            unsigned a3 = As[(wrow0 + lq + 8) * 36 + kw + 4];
#pragma unroll
            for (int j = 0; j < 4; j++) {
                unsigned b0 = Bs[(ncol0 + 8 * j + lq) * 36 + kw];
                unsigned b1 = Bs[(ncol0 + 8 * j + lq) * 36 + kw + 4];
                asm volatile(
                    "mma.sync.aligned.m16n8k16.row.col.f32.bf16.bf16.f32 "
                    "{%0,%1,%2,%3}, {%4,%5,%6,%7}, {%8,%9}, {%0,%1,%2,%3};"
                    : "+f"(c[j][0]), "+f"(c[j][1]), "+f"(c[j][2]), "+f"(c[j][3])
                    : "r"(a0), "r"(a1), "r"(a2), "r"(a3), "r"(b0), "r"(b1));
            }
        }
        __syncthreads();
    }

    // --- write bf16x2 output ---
    {
        const int r0 = row0 + wrow0 + lq;
        const int r1 = r0 + 8;
#pragma unroll
        for (int j = 0; j < 4; j++) {
            unsigned wlo = bf16x2_of(c[j][1], c[j][0]);
            unsigned whi = bf16x2_of(c[j][3], c[j][2]);
            int wcol = (ncol0 >> 1) + 4 * j + lr4;
            if (r0 < N_NODES) g_xw[(size_t)r0 * 32 + wcol] = wlo;
            if (r1 < N_NODES) g_xw[(size_t)r1 * 32 + wcol] = whi;
        }
    }
}

// ---------------------------------------------------------------------------
// Launch 2: fused bucket gather + tanh + l2-normalize + sum(emb^2).
// One warp per row. Also RESETS g_cnt[row]=0 so no memset is needed.
// ---------------------------------------------------------------------------
__global__ __launch_bounds__(256) void row_kernel() {
    __shared__ int2  stage[8][32];
    __shared__ float ssum;
    const int wib  = threadIdx.x >> 5;
    const int row  = (blockIdx.x * 256 + threadIdx.x) >> 5;
    const int lane = threadIdx.x & 31;
    const int grp  = lane >> 3;
    const int subw = (lane & 7) << 2;       // word offset of this lane's 4 words
    if (threadIdx.x == 0) ssum = 0.f;
    __syncthreads();

    if (row < N_NODES) {
        const int len = min(g_cnt[row], CAP);
        if (lane == 0) g_cnt[row] = 0;       // self-clean for next graph replay
        const int2* __restrict__ bucket = &g_csr[(size_t)row * CAP];
        float acc[8];
#pragma unroll
        for (int k = 0; k < 8; k++) acc[k] = 0.f;

        for (int base = 0; base < len; base += 32) {
            int j = base + lane;
            stage[wib][lane] = (j < len) ? bucket[j] : make_int2(0, 0);
            __syncwarp();
            int m4 = (min(32, len - base) + 3) & ~3;    // val=0 pads are no-ops
            for (int t = 0; t < m4; t += 4) {
                int2 cv = stage[wib][t + grp];
                const uint4 u = *(const uint4*)(g_xw + (unsigned)(cv.x * 32) + subw);
                float v = __int_as_float(cv.y);
                acc[0] = fmaf(v, __uint_as_float(u.x << 16),          acc[0]);
                acc[1] = fmaf(v, __uint_as_float(u.x & 0xffff0000u),  acc[1]);
                acc[2] = fmaf(v, __uint_as_float(u.y << 16),          acc[2]);
                acc[3] = fmaf(v, __uint_as_float(u.y & 0xffff0000u),  acc[3]);
                acc[4] = fmaf(v, __uint_as_float(u.z << 16),          acc[4]);
                acc[5] = fmaf(v, __uint_as_float(u.z & 0xffff0000u),  acc[5]);
                acc[6] = fmaf(v, __uint_as_float(u.w << 16),          acc[6]);
                acc[7] = fmaf(v, __uint_as_float(u.w & 0xffff0000u),  acc[7]);
            }
            __syncwarp();
        }

        // combine the 4 edge groups (lane bits 3,4)
#pragma unroll
        for (int k = 0; k < 8; k++) {
            acc[k] += __shfl_xor_sync(0xffffffffu, acc[k], 8);
            acc[k] += __shfl_xor_sync(0xffffffffu, acc[k], 16);
        }
        float h[8];
        float sq = 0.f;
#pragma unroll
        for (int k = 0; k < 8; k++) { h[k] = tanhf(acc[k]); sq = fmaf(h[k], h[k], sq); }
#pragma unroll
        for (int o = 1; o < 8; o <<= 1) sq += __shfl_xor_sync(0xffffffffu, sq, o);
        float rs = rsqrtf(fmaxf(sq, 1e-12f));
        if (grp == 0) {   // lanes 0..7 write the full 64-dim row
            *(float4*)&g_h[(size_t)row * EMB_DIM + subw * 2] =
                make_float4(h[0] * rs, h[1] * rs, h[2] * rs, h[3] * rs);
            *(float4*)&g_h[(size_t)row * EMB_DIM + subw * 2 + 4] =
                make_float4(h[4] * rs, h[5] * rs, h[6] * rs, h[7] * rs);
        }
        // weight decay needs sum over NORMALIZED emb: sq * rs^2
        if (lane == 0) atomicAdd(&ssum, sq * rs * rs);
    }
    __syncthreads();
    if (threadIdx.x == 0) atomicAdd(&g_acc[0], ssum);
}

// ---------------------------------------------------------------------------
// Launch 3: BPR loss + fused finalize (last block writes the scalar out).
// ---------------------------------------------------------------------------
__global__ __launch_bounds__(256) void loss_kernel(const int* __restrict__ idx1,
                                                   const int* __restrict__ idx2,
                                                   const int* __restrict__ negi,
                                                   float* __restrict__ out) {
    int b    = (blockIdx.x * blockDim.x + threadIdx.x) >> 5;
    int lane = threadIdx.x & 31;
    __shared__ float ssum;
    if (threadIdx.x == 0) ssum = 0.f;
    __syncthreads();

    if (b < BATCH) {
        int i1 = idx1[b], i2 = idx2[b], in_ = negi[b];
        float2 e1 = *(float2*)&g_h[(size_t)i1 * EMB_DIM + lane * 2];
        float2 e2 = *(float2*)&g_h[(size_t)i2 * EMB_DIM + lane * 2];
        float2 en = *(float2*)&g_h[(size_t)in_ * EMB_DIM + lane * 2];
        float dui = e1.x * e2.x + e1.y * e2.y;
        float duj = e1.x * en.x + e1.y * en.y;
#pragma unroll
        for (int o = 16; o > 0; o >>= 1) {
            dui += __shfl_xor_sync(0xffffffffu, dui, o);
            duj += __shfl_xor_sync(0xffffffffu, duj, o);
        }
        if (lane == 0) {
            float z = duj - dui;  // -log_sigmoid(dui-duj) = softplus(duj-dui)
            float term = fmaxf(z, 0.f) + log1pf(expf(-fabsf(z)));
            atomicAdd(&ssum, term);
        }
    }
    __syncthreads();
    if (threadIdx.x == 0) {
        atomicAdd(&g_acc[1], ssum);
        __threadfence();
        int d = atomicAdd(&g_done, 1);
        if (d == (int)gridDim.x - 1) {
            float bpr = atomicAdd(&g_acc[1], 0.f);   // L2-coherent reads
            float ss  = atomicAdd(&g_acc[0], 0.f);
            out[0] = (bpr + 1e-4f * 0.5f * ss) / (float)BATCH;
        }
    }
}

// ---------------------------------------------------------------------------
extern "C" void kernel_launch(void* const* d_in, const int* in_sizes, int n_in,
                              void* d_out, int out_size) {
    const float* feats = (const float*)d_in[0];
    const float* W     = (const float*)d_in[1];
    const int*   erow  = (const int*)d_in[2];
    const int*   ecol  = (const int*)d_in[3];
    const float* evalv = (const float*)d_in[4];
    const int*   idx1  = (const int*)d_in[5];
    const int*   idx2  = (const int*)d_in[6];
    const int*   negi  = (const int*)d_in[7];

    prep_kernel<<<32, 256>>>(W);
    gemm_scatter_kernel<<<NFUSED, 256>>>(feats, erow, ecol, evalv);
    row_kernel<<<(N_NODES * 32 + 255) / 256, 256>>>();
    loss_kernel<<<(BATCH * 32) / 256, 256>>>(idx1, idx2, negi, (float*)d_out);
}

// round 14
// speedup vs baseline: 1.6487x; 1.3654x over previous
#include <cuda_runtime.h>
#include <math.h>

#define N_NODES 100000
#define N_EDGES 3200000
#define IN_DIM 256
#define EMB_DIM 64
#define BATCH 4096
#define CAP 96                                       // bucket capacity per row

#define TILE_M 64
#define NGEMM ((N_NODES + TILE_M - 1) / TILE_M)     // 1563 gemm tiles
#define NFUSED (NGEMM * 2)                          // interleaved gemm/scatter blocks

// ---------------- device scratch (no allocation allowed) ----------------
__device__ unsigned  g_xw[(size_t)N_NODES * 32];    // bf16x2 packed, 2 dims/word
__device__ unsigned  g_wb[EMB_DIM * 128];           // W bf16x2, [n][kword], 32KB
__device__ float     g_h[(size_t)N_NODES * EMB_DIM];
__device__ int       g_cnt[N_NODES];                // bucket cursor == row degree
__device__ int2      g_csr[(size_t)N_NODES * CAP];  // {col, float_bits(val)} buckets
__device__ int       g_done;
__device__ float     g_acc[2];                      // [0]=sum(emb^2), [1]=bpr

static __device__ __forceinline__ unsigned bf16x2_of(float hi, float lo) {
    unsigned r;
    asm("cvt.rn.bf16x2.f32 %0, %1, %2;" : "=r"(r) : "f"(hi), "f"(lo));
    return r;
}

// ---------------------------------------------------------------------------
// Launch 0 (tiny, 32 blocks): convert W (256x64 fp32) -> g_wb[n][kword]
// bf16x2 frag layout.
// ---------------------------------------------------------------------------
__global__ void prep_kernel(const float* __restrict__ W) {
    int idx = blockIdx.x * 256 + threadIdx.x;        // 8192 total
    if (idx < EMB_DIM * 128) {
        int n  = idx >> 7;          // 0..63
        int kw = idx & 127;         // k-pair 0..127
        float lo = W[(size_t)(2 * kw)     * EMB_DIM + n];
        float hi = W[(size_t)(2 * kw + 1) * EMB_DIM + n];
        g_wb[n * 128 + kw] = bf16x2_of(hi, lo);
    }
}

// ---------------------------------------------------------------------------
// Launch 1 (FUSED): even blocks = 64x64 HMMA GEMM tile, odd blocks = bucket
// scatter (4 edges/thread, vector loads, independent atomics). This is the
// R9 kernel (148.2us total, fused 78.8us) with EXACTLY ONE change: the B
// smem tile is filled by plain uint4 copies from pre-converted g_wb instead
// of per-block load+cvt+transpose. Everything else byte-identical to R9.
// ---------------------------------------------------------------------------
__global__ __launch_bounds__(256, 5) void gemm_scatter_kernel(
        const float* __restrict__ feats,
        const int* __restrict__ erow, const int* __restrict__ ecol,
        const float* __restrict__ evalv) {
    if (blockIdx.x == 0 && threadIdx.x == 0) {
        g_acc[0] = 0.f; g_acc[1] = 0.f; g_done = 0;
    }
    if (blockIdx.x & 1) {
        // ---- scatter role: 4 consecutive edges per thread via 128b loads ----
        const int nquads  = N_EDGES / 4;              // 800000
        const int qstride = NGEMM * 256;              // total scatter threads
        for (int q = (blockIdx.x >> 1) * 256 + threadIdx.x; q < nquads; q += qstride) {
            int4   r4 = ((const int4*)erow)[q];
            int4   c4 = ((const int4*)ecol)[q];
            float4 v4 = ((const float4*)evalv)[q];
            int p0 = atomicAdd(&g_cnt[r4.x], 1);
            int p1 = atomicAdd(&g_cnt[r4.y], 1);
            int p2 = atomicAdd(&g_cnt[r4.z], 1);
            int p3 = atomicAdd(&g_cnt[r4.w], 1);
            if (p0 < CAP) g_csr[(size_t)r4.x * CAP + p0] = make_int2(c4.x, __float_as_int(v4.x));
            if (p1 < CAP) g_csr[(size_t)r4.y * CAP + p1] = make_int2(c4.y, __float_as_int(v4.y));
            if (p2 < CAP) g_csr[(size_t)r4.z * CAP + p2] = make_int2(c4.z, __float_as_int(v4.z));
            if (p3 < CAP) g_csr[(size_t)r4.w * CAP + p3] = make_int2(c4.w, __float_as_int(v4.w));
        }
        return;
    }

    // ---- GEMM role: xw[row0..row0+63][0..63] via mma.m16n8k16 bf16 ----
    __shared__ __align__(16) unsigned As[TILE_M * 36];   // A: [row][kword]
    __shared__ __align__(16) unsigned Bs[EMB_DIM * 36];  // B: [n][kword]

    const int row0 = (blockIdx.x >> 1) * TILE_M;
    const int tid  = threadIdx.x;
    const int wp   = tid >> 5;          // 0..7
    const int l    = tid & 31;
    const int lq   = l >> 2;            // 0..7
    const int lr4  = l & 3;             // 0..3
    const int wrow0 = (wp & 3) * 16;
    const int ncol0 = (wp >> 2) * 32;   // 0 or 32

    float c[4][4];
#pragma unroll
    for (int j = 0; j < 4; j++)
#pragma unroll
        for (int q = 0; q < 4; q++) c[j][q] = 0.f;

    for (int kb = 0; kb < IN_DIM; kb += 64) {
        // --- fill A: 64 rows x 64 k (fp32 -> bf16x2). 4 threads/row. (R9) ---
        {
            const int r    = tid >> 2;                // 0..63
            const int part = tid & 3;                 // 4 float4s each
            const int grow = row0 + r;
            const float* src = &feats[(size_t)grow * IN_DIM + kb];
#pragma unroll
            for (int i = 0; i < 4; i++) {
                int j4 = part * 4 + i;                // float4 index 0..15
                float4 f = make_float4(0.f, 0.f, 0.f, 0.f);
                if (grow < N_NODES) f = *(const float4*)(src + 4 * j4);
                uint2 w2 = make_uint2(bf16x2_of(f.y, f.x), bf16x2_of(f.w, f.z));
                *(uint2*)&As[r * 36 + 2 * j4] = w2;
            }
        }
        // --- fill B: straight uint4 copy from pre-converted g_wb (ONLY delta)
        {
            const int kwg0 = kb >> 1;              // first global kword this kb
#pragma unroll
            for (int s = tid; s < 512; s += 256) {
                int n  = s >> 3;                   // 0..63
                int wq = s & 7;                    // uint4 index (4 kwords)
                uint4 v = *(const uint4*)&g_wb[n * 128 + kwg0 + 4 * wq];
                *(uint4*)&Bs[n * 36 + 4 * wq] = v;
            }
        }
        __syncthreads();

        // --- 4 k-steps of 16 ---
#pragma unroll
        for (int ks = 0; ks < 4; ks++) {
            const int kw = ks * 8 + lr4;
            unsigned a0 = As[(wrow0 + lq) * 36 + kw];
            unsigned a1 = As[(wrow0 + lq + 8) * 36 + kw];
            unsigned a2 = As[(wrow0 + lq) * 36 + kw + 4];
            unsigned a3 = As[(wrow0 + lq + 8) * 36 + kw + 4];
#pragma unroll
            for (int j = 0; j < 4; j++) {
                unsigned b0 = Bs[(ncol0 + 8 * j + lq) * 36 + kw];
                unsigned b1 = Bs[(ncol0 + 8 * j + lq) * 36 + kw + 4];
                asm volatile(
                    "mma.sync.aligned.m16n8k16.row.col.f32.bf16.bf16.f32 "
                    "{%0,%1,%2,%3}, {%4,%5,%6,%7}, {%8,%9}, {%0,%1,%2,%3};"
                    : "+f"(c[j][0]), "+f"(c[j][1]), "+f"(c[j][2]), "+f"(c[j][3])
                    : "r"(a0), "r"(a1), "r"(a2), "r"(a3), "r"(b0), "r"(b1));
            }
        }
        __syncthreads();
    }

    // --- write bf16x2 output ---
    {
        const int r0 = row0 + wrow0 + lq;
        const int r1 = r0 + 8;
#pragma unroll
        for (int j = 0; j < 4; j++) {
            unsigned wlo = bf16x2_of(c[j][1], c[j][0]);
            unsigned whi = bf16x2_of(c[j][3], c[j][2]);
            int wcol = (ncol0 >> 1) + 4 * j + lr4;
            if (r0 < N_NODES) g_xw[(size_t)r0 * 32 + wcol] = wlo;
            if (r1 < N_NODES) g_xw[(size_t)r1 * 32 + wcol] = whi;
        }
    }
}

// ---------------------------------------------------------------------------
// Launch 2: fused bucket gather + tanh + l2-normalize + sum(emb^2). (R9)
// ---------------------------------------------------------------------------
__global__ __launch_bounds__(256) void row_kernel() {
    __shared__ int2  stage[8][32];
    __shared__ float ssum;
    const int wib  = threadIdx.x >> 5;
    const int row  = (blockIdx.x * 256 + threadIdx.x) >> 5;
    const int lane = threadIdx.x & 31;
    const int grp  = lane >> 3;
    const int subw = (lane & 7) << 2;       // word offset of this lane's 4 words
    if (threadIdx.x == 0) ssum = 0.f;
    __syncthreads();

    if (row < N_NODES) {
        const int len = min(g_cnt[row], CAP);
        const int2* __restrict__ bucket = &g_csr[(size_t)row * CAP];
        float acc[8];
#pragma unroll
        for (int k = 0; k < 8; k++) acc[k] = 0.f;

        for (int base = 0; base < len; base += 32) {
            int j = base + lane;
            stage[wib][lane] = (j < len) ? bucket[j] : make_int2(0, 0);
            __syncwarp();
            int m4 = (min(32, len - base) + 3) & ~3;    // val=0 pads are no-ops
            for (int t = 0; t < m4; t += 4) {
                int2 cv = stage[wib][t + grp];
                const uint4 u = *(const uint4*)(g_xw + (unsigned)(cv.x * 32) + subw);
                float v = __int_as_float(cv.y);
                acc[0] = fmaf(v, __uint_as_float(u.x << 16),          acc[0]);
                acc[1] = fmaf(v, __uint_as_float(u.x & 0xffff0000u),  acc[1]);
                acc[2] = fmaf(v, __uint_as_float(u.y << 16),          acc[2]);
                acc[3] = fmaf(v, __uint_as_float(u.y & 0xffff0000u),  acc[3]);
                acc[4] = fmaf(v, __uint_as_float(u.z << 16),          acc[4]);
                acc[5] = fmaf(v, __uint_as_float(u.z & 0xffff0000u),  acc[5]);
                acc[6] = fmaf(v, __uint_as_float(u.w << 16),          acc[6]);
                acc[7] = fmaf(v, __uint_as_float(u.w & 0xffff0000u),  acc[7]);
            }
            __syncwarp();
        }

        // combine the 4 edge groups (lane bits 3,4)
#pragma unroll
        for (int k = 0; k < 8; k++) {
            acc[k] += __shfl_xor_sync(0xffffffffu, acc[k], 8);
            acc[k] += __shfl_xor_sync(0xffffffffu, acc[k], 16);
        }
        float h[8];
        float sq = 0.f;
#pragma unroll
        for (int k = 0; k < 8; k++) { h[k] = tanhf(acc[k]); sq = fmaf(h[k], h[k], sq); }
#pragma unroll
        for (int o = 1; o < 8; o <<= 1) sq += __shfl_xor_sync(0xffffffffu, sq, o);
        float rs = rsqrtf(fmaxf(sq, 1e-12f));
        if (grp == 0) {   // lanes 0..7 write the full 64-dim row
            *(float4*)&g_h[(size_t)row * EMB_DIM + subw * 2] =
                make_float4(h[0] * rs, h[1] * rs, h[2] * rs, h[3] * rs);
            *(float4*)&g_h[(size_t)row * EMB_DIM + subw * 2 + 4] =
                make_float4(h[4] * rs, h[5] * rs, h[6] * rs, h[7] * rs);
        }
        // weight decay needs sum over NORMALIZED emb: sq * rs^2
        if (lane == 0) atomicAdd(&ssum, sq * rs * rs);
    }
    __syncthreads();
    if (threadIdx.x == 0) atomicAdd(&g_acc[0], ssum);
}

// ---------------------------------------------------------------------------
// Launch 3: BPR loss + fused finalize (last block writes the scalar out). (R9)
// ---------------------------------------------------------------------------
__global__ __launch_bounds__(256) void loss_kernel(const int* __restrict__ idx1,
                                                   const int* __restrict__ idx2,
                                                   const int* __restrict__ negi,
                                                   float* __restrict__ out) {
    int b    = (blockIdx.x * blockDim.x + threadIdx.x) >> 5;
    int lane = threadIdx.x & 31;
    __shared__ float ssum;
    if (threadIdx.x == 0) ssum = 0.f;
    __syncthreads();

    if (b < BATCH) {
        int i1 = idx1[b], i2 = idx2[b], in_ = negi[b];
        float2 e1 = *(float2*)&g_h[(size_t)i1 * EMB_DIM + lane * 2];
        float2 e2 = *(float2*)&g_h[(size_t)i2 * EMB_DIM + lane * 2];
        float2 en = *(float2*)&g_h[(size_t)in_ * EMB_DIM + lane * 2];
        float dui = e1.x * e2.x + e1.y * e2.y;
        float duj = e1.x * en.x + e1.y * en.y;
#pragma unroll
        for (int o = 16; o > 0; o >>= 1) {
            dui += __shfl_xor_sync(0xffffffffu, dui, o);
            duj += __shfl_xor_sync(0xffffffffu, duj, o);
        }
        if (lane == 0) {
            float z = duj - dui;  // -log_sigmoid(dui-duj) = softplus(duj-dui)
            float term = fmaxf(z, 0.f) + log1pf(expf(-fabsf(z)));
            atomicAdd(&ssum, term);
        }
    }
    __syncthreads();
    if (threadIdx.x == 0) {
        atomicAdd(&g_acc[1], ssum);
        __threadfence();
        int d = atomicAdd(&g_done, 1);
        if (d == (int)gridDim.x - 1) {
            float bpr = atomicAdd(&g_acc[1], 0.f);   // L2-coherent reads
            float ss  = atomicAdd(&g_acc[0], 0.f);
            out[0] = (bpr + 1e-4f * 0.5f * ss) / (float)BATCH;
        }
    }
}

// ---------------------------------------------------------------------------
extern "C" void kernel_launch(void* const* d_in, const int* in_sizes, int n_in,
                              void* d_out, int out_size) {
    const float* feats = (const float*)d_in[0];
    const float* W     = (const float*)d_in[1];
    const int*   erow  = (const int*)d_in[2];
    const int*   ecol  = (const int*)d_in[3];
    const float* evalv = (const float*)d_in[4];
    const int*   idx1  = (const int*)d_in[5];
    const int*   idx2  = (const int*)d_in[6];
    const int*   negi  = (const int*)d_in[7];

    void* cntp;
    cudaGetSymbolAddress(&cntp, g_cnt);
    cudaMemsetAsync(cntp, 0, sizeof(int) * N_NODES);

    prep_kernel<<<32, 256>>>(W);
    gemm_scatter_kernel<<<NFUSED, 256>>>(feats, erow, ecol, evalv);
    row_kernel<<<(N_NODES * 32 + 255) / 256, 256>>>();
    loss_kernel<<<(BATCH * 32) / 256, 256>>>(idx1, idx2, negi, (float*)d_out);
}

// round 15
// speedup vs baseline: 1.7257x; 1.0467x over previous
#include <cuda_runtime.h>
#include <math.h>

#define N_NODES 100000
#define N_EDGES 3200000
#define IN_DIM 256
#define EMB_DIM 64
#define BATCH 4096
#define CAP 96                                       // bucket capacity per row

#define TILE_M 64
#define NGEMM ((N_NODES + TILE_M - 1) / TILE_M)     // 1563 gemm tiles
#define NFUSED (NGEMM * 2)                          // interleaved gemm/scatter blocks

// ---------------- device scratch (no allocation allowed) ----------------
__device__ unsigned  g_xw[(size_t)N_NODES * 32];    // bf16x2 packed, 2 dims/word
__device__ unsigned  g_wb[EMB_DIM * 128];           // W bf16x2, [n][kword], 32KB
__device__ float     g_h[(size_t)N_NODES * EMB_DIM];
__device__ int       g_cnt[N_NODES];                // bucket cursor == row degree
__device__ int2      g_csr[(size_t)N_NODES * CAP];  // {col, float_bits(val)} buckets
__device__ int       g_done;
__device__ float     g_acc[2];                      // [0]=sum(emb^2), [1]=bpr

static __device__ __forceinline__ unsigned bf16x2_of(float hi, float lo) {
    unsigned r;
    asm("cvt.rn.bf16x2.f32 %0, %1, %2;" : "=r"(r) : "f"(hi), "f"(lo));
    return r;
}

// ---------------------------------------------------------------------------
// Launch 0 (391 blocks): convert W -> g_wb bf16x2 frag layout, zero g_cnt
// (replaces the memset node), zero scalar state.
// ---------------------------------------------------------------------------
__global__ void prep_kernel(const float* __restrict__ W) {
    int idx = blockIdx.x * 256 + threadIdx.x;
    if (idx == 0) { g_acc[0] = 0.f; g_acc[1] = 0.f; g_done = 0; }
    if (idx < EMB_DIM * 128) {           // 8192 conversion slots
        int n  = idx >> 7;               // 0..63
        int kw = idx & 127;              // k-pair 0..127
        float lo = W[(size_t)(2 * kw)     * EMB_DIM + n];
        float hi = W[(size_t)(2 * kw + 1) * EMB_DIM + n];
        g_wb[n * 128 + kw] = bf16x2_of(hi, lo);
    }
    if (idx < N_NODES) g_cnt[idx] = 0;
}

// ---------------------------------------------------------------------------
// Launch 1 (FUSED): even blocks = 64x64 HMMA GEMM tile, odd blocks = bucket
// scatter (4 edges/thread, vector loads, independent atomics). R14 structure
// (139.8us): R9 GEMM with B smem tile filled by uint4 copies from g_wb.
// ---------------------------------------------------------------------------
__global__ __launch_bounds__(256, 5) void gemm_scatter_kernel(
        const float* __restrict__ feats,
        const int* __restrict__ erow, const int* __restrict__ ecol,
        const float* __restrict__ evalv) {
    if (blockIdx.x & 1) {
        // ---- scatter role: 4 consecutive edges per thread via 128b loads ----
        const int nquads  = N_EDGES / 4;              // 800000
        const int qstride = NGEMM * 256;              // total scatter threads
        for (int q = (blockIdx.x >> 1) * 256 + threadIdx.x; q < nquads; q += qstride) {
            int4   r4 = ((const int4*)erow)[q];
            int4   c4 = ((const int4*)ecol)[q];
            float4 v4 = ((const float4*)evalv)[q];
            int p0 = atomicAdd(&g_cnt[r4.x], 1);
            int p1 = atomicAdd(&g_cnt[r4.y], 1);
            int p2 = atomicAdd(&g_cnt[r4.z], 1);
            int p3 = atomicAdd(&g_cnt[r4.w], 1);
            if (p0 < CAP) g_csr[(size_t)r4.x * CAP + p0] = make_int2(c4.x, __float_as_int(v4.x));
            if (p1 < CAP) g_csr[(size_t)r4.y * CAP + p1] = make_int2(c4.y, __float_as_int(v4.y));
            if (p2 < CAP) g_csr[(size_t)r4.z * CAP + p2] = make_int2(c4.z, __float_as_int(v4.z));
            if (p3 < CAP) g_csr[(size_t)r4.w * CAP + p3] = make_int2(c4.w, __float_as_int(v4.w));
        }
        return;
    }

    // ---- GEMM role: xw[row0..row0+63][0..63] via mma.m16n8k16 bf16 ----
    __shared__ __align__(16) unsigned As[TILE_M * 36];   // A: [row][kword]
    __shared__ __align__(16) unsigned Bs[EMB_DIM * 36];  // B: [n][kword]

    const int row0 = (blockIdx.x >> 1) * TILE_M;
    const int tid  = threadIdx.x;
    const int wp   = tid >> 5;          // 0..7
    const int l    = tid & 31;
    const int lq   = l >> 2;            // 0..7
    const int lr4  = l & 3;             // 0..3
    const int wrow0 = (wp & 3) * 16;
    const int ncol0 = (wp >> 2) * 32;   // 0 or 32

    float c[4][4];
#pragma unroll
    for (int j = 0; j < 4; j++)
#pragma unroll
        for (int q = 0; q < 4; q++) c[j][q] = 0.f;

    for (int kb = 0; kb < IN_DIM; kb += 64) {
        // --- fill A: 64 rows x 64 k (fp32 -> bf16x2). 4 threads/row. ---
        {
            const int r    = tid >> 2;                // 0..63
            const int part = tid & 3;                 // 4 float4s each
            const int grow = row0 + r;
            const float* src = &feats[(size_t)grow * IN_DIM + kb];
#pragma unroll
            for (int i = 0; i < 4; i++) {
                int j4 = part * 4 + i;                // float4 index 0..15
                float4 f = make_float4(0.f, 0.f, 0.f, 0.f);
                if (grow < N_NODES) f = *(const float4*)(src + 4 * j4);
                uint2 w2 = make_uint2(bf16x2_of(f.y, f.x), bf16x2_of(f.w, f.z));
                *(uint2*)&As[r * 36 + 2 * j4] = w2;
            }
        }
        // --- fill B: straight uint4 copy from pre-converted g_wb ---
        {
            const int kwg0 = kb >> 1;              // first global kword this kb
#pragma unroll
            for (int s = tid; s < 512; s += 256) {
                int n  = s >> 3;                   // 0..63
                int wq = s & 7;                    // uint4 index (4 kwords)
                uint4 v = *(const uint4*)&g_wb[n * 128 + kwg0 + 4 * wq];
                *(uint4*)&Bs[n * 36 + 4 * wq] = v;
            }
        }
        __syncthreads();

        // --- 4 k-steps of 16 ---
#pragma unroll
        for (int ks = 0; ks < 4; ks++) {
            const int kw = ks * 8 + lr4;
            unsigned a0 = As[(wrow0 + lq) * 36 + kw];
            unsigned a1 = As[(wrow0 + lq + 8) * 36 + kw];
            unsigned a2 = As[(wrow0 + lq) * 36 + kw + 4];
            unsigned a3 = As[(wrow0 + lq + 8) * 36 + kw + 4];
#pragma unroll
            for (int j = 0; j < 4; j++) {
                unsigned b0 = Bs[(ncol0 + 8 * j + lq) * 36 + kw];
                unsigned b1 = Bs[(ncol0 + 8 * j + lq) * 36 + kw + 4];
                asm volatile(
                    "mma.sync.aligned.m16n8k16.row.col.f32.bf16.bf16.f32 "
                    "{%0,%1,%2,%3}, {%4,%5,%6,%7}, {%8,%9}, {%0,%1,%2,%3};"
                    : "+f"(c[j][0]), "+f"(c[j][1]), "+f"(c[j][2]), "+f"(c[j][3])
                    : "r"(a0), "r"(a1), "r"(a2), "r"(a3), "r"(b0), "r"(b1));
            }
        }
        __syncthreads();
    }

    // --- write bf16x2 output ---
    {
        const int r0 = row0 + wrow0 + lq;
        const int r1 = r0 + 8;
#pragma unroll
        for (int j = 0; j < 4; j++) {
            unsigned wlo = bf16x2_of(c[j][1], c[j][0]);
            unsigned whi = bf16x2_of(c[j][3], c[j][2]);
            int wcol = (ncol0 >> 1) + 4 * j + lr4;
            if (r0 < N_NODES) g_xw[(size_t)r0 * 32 + wcol] = wlo;
            if (r1 < N_NODES) g_xw[(size_t)r1 * 32 + wcol] = whi;
        }
    }
}

// ---------------------------------------------------------------------------
// Launch 2: fused bucket gather + tanh + l2-normalize + sum(emb^2).
// Inner edge loop unrolled 2x for doubled gather MLP.
// ---------------------------------------------------------------------------
__global__ __launch_bounds__(256) void row_kernel() {
    __shared__ int2  stage[8][32];
    __shared__ float ssum;
    const int wib  = threadIdx.x >> 5;
    const int row  = (blockIdx.x * 256 + threadIdx.x) >> 5;
    const int lane = threadIdx.x & 31;
    const int grp  = lane >> 3;
    const int subw = (lane & 7) << 2;       // word offset of this lane's 4 words
    if (threadIdx.x == 0) ssum = 0.f;
    __syncthreads();

    if (row < N_NODES) {
        const int len = min(g_cnt[row], CAP);
        const int2* __restrict__ bucket = &g_csr[(size_t)row * CAP];
        float acc[8];
#pragma unroll
        for (int k = 0; k < 8; k++) acc[k] = 0.f;

        for (int base = 0; base < len; base += 32) {
            int j = base + lane;
            stage[wib][lane] = (j < len) ? bucket[j] : make_int2(0, 0);
            __syncwarp();
            int m4 = (min(32, len - base) + 3) & ~3;    // val=0 pads are no-ops
#pragma unroll 2
            for (int t = 0; t < m4; t += 4) {
                int2 cv = stage[wib][t + grp];
                const uint4 u = *(const uint4*)(g_xw + (unsigned)(cv.x * 32) + subw);
                float v = __int_as_float(cv.y);
                acc[0] = fmaf(v, __uint_as_float(u.x << 16),          acc[0]);
                acc[1] = fmaf(v, __uint_as_float(u.x & 0xffff0000u),  acc[1]);
                acc[2] = fmaf(v, __uint_as_float(u.y << 16),          acc[2]);
                acc[3] = fmaf(v, __uint_as_float(u.y & 0xffff0000u),  acc[3]);
                acc[4] = fmaf(v, __uint_as_float(u.z << 16),          acc[4]);
                acc[5] = fmaf(v, __uint_as_float(u.z & 0xffff0000u),  acc[5]);
                acc[6] = fmaf(v, __uint_as_float(u.w << 16),          acc[6]);
                acc[7] = fmaf(v, __uint_as_float(u.w & 0xffff0000u),  acc[7]);
            }
            __syncwarp();
        }

        // combine the 4 edge groups (lane bits 3,4)
#pragma unroll
        for (int k = 0; k < 8; k++) {
            acc[k] += __shfl_xor_sync(0xffffffffu, acc[k], 8);
            acc[k] += __shfl_xor_sync(0xffffffffu, acc[k], 16);
        }
        float h[8];
        float sq = 0.f;
#pragma unroll
        for (int k = 0; k < 8; k++) { h[k] = tanhf(acc[k]); sq = fmaf(h[k], h[k], sq); }
#pragma unroll
        for (int o = 1; o < 8; o <<= 1) sq += __shfl_xor_sync(0xffffffffu, sq, o);
        float rs = rsqrtf(fmaxf(sq, 1e-12f));
        if (grp == 0) {   // lanes 0..7 write the full 64-dim row
            *(float4*)&g_h[(size_t)row * EMB_DIM + subw * 2] =
                make_float4(h[0] * rs, h[1] * rs, h[2] * rs, h[3] * rs);
            *(float4*)&g_h[(size_t)row * EMB_DIM + subw * 2 + 4] =
                make_float4(h[4] * rs, h[5] * rs, h[6] * rs, h[7] * rs);
        }
        // weight decay needs sum over NORMALIZED emb: sq * rs^2
        if (lane == 0) atomicAdd(&ssum, sq * rs * rs);
    }
    __syncthreads();
    if (threadIdx.x == 0) atomicAdd(&g_acc[0], ssum);
}

// ---------------------------------------------------------------------------
// Launch 3: BPR loss + fused finalize. 4 batch elements per warp (MLP x4,
// grid 128 blocks instead of 512).
// ---------------------------------------------------------------------------
__global__ __launch_bounds__(256) void loss_kernel(const int* __restrict__ idx1,
                                                   const int* __restrict__ idx2,
                                                   const int* __restrict__ negi,
                                                   float* __restrict__ out) {
    int warp = (blockIdx.x * blockDim.x + threadIdx.x) >> 5;   // 0..1023
    int lane = threadIdx.x & 31;
    int b0   = warp * 4;
    __shared__ float ssum;
    if (threadIdx.x == 0) ssum = 0.f;
    __syncthreads();

    float dui[4], duj[4];
#pragma unroll
    for (int k = 0; k < 4; k++) {
        int b = b0 + k;
        float2 e1 = *(float2*)&g_h[(size_t)idx1[b] * EMB_DIM + lane * 2];
        float2 e2 = *(float2*)&g_h[(size_t)idx2[b] * EMB_DIM + lane * 2];
        float2 en = *(float2*)&g_h[(size_t)negi[b] * EMB_DIM + lane * 2];
        dui[k] = e1.x * e2.x + e1.y * e2.y;
        duj[k] = e1.x * en.x + e1.y * en.y;
    }
#pragma unroll
    for (int o = 16; o > 0; o >>= 1)
#pragma unroll
        for (int k = 0; k < 4; k++) {
            dui[k] += __shfl_xor_sync(0xffffffffu, dui[k], o);
            duj[k] += __shfl_xor_sync(0xffffffffu, duj[k], o);
        }
    if (lane == 0) {
        float s = 0.f;
#pragma unroll
        for (int k = 0; k < 4; k++) {
            float z = duj[k] - dui[k];   // softplus(duj-dui)
            s += fmaxf(z, 0.f) + log1pf(expf(-fabsf(z)));
        }
        atomicAdd(&ssum, s);
    }
    __syncthreads();
    if (threadIdx.x == 0) {
        atomicAdd(&g_acc[1], ssum);
        __threadfence();
        int d = atomicAdd(&g_done, 1);
        if (d == (int)gridDim.x - 1) {
            float bpr = atomicAdd(&g_acc[1], 0.f);   // L2-coherent reads
            float ss  = atomicAdd(&g_acc[0], 0.f);
            out[0] = (bpr + 1e-4f * 0.5f * ss) / (float)BATCH;
        }
    }
}

// ---------------------------------------------------------------------------
extern "C" void kernel_launch(void* const* d_in, const int* in_sizes, int n_in,
                              void* d_out, int out_size) {
    const float* feats = (const float*)d_in[0];
    const float* W     = (const float*)d_in[1];
    const int*   erow  = (const int*)d_in[2];
    const int*   ecol  = (const int*)d_in[3];
    const float* evalv = (const float*)d_in[4];
    const int*   idx1  = (const int*)d_in[5];
    const int*   idx2  = (const int*)d_in[6];
    const int*   negi  = (const int*)d_in[7];

    prep_kernel<<<(N_NODES + 255) / 256, 256>>>(W);
    gemm_scatter_kernel<<<NFUSED, 256>>>(feats, erow, ecol, evalv);
    row_kernel<<<(N_NODES * 32 + 255) / 256, 256>>>();
    loss_kernel<<<(BATCH / 4 * 32) / 256, 256>>>(idx1, idx2, negi, (float*)d_out);
}